// round 2
// baseline (speedup 1.0000x reference)
#include <cuda_runtime.h>
#include <cstdint>
#include <math.h>

// Problem constants
#define Bc   4
#define Tc   4096
#define HIDc 1024
#define NHc  16
#define QKc  64
#define VDc  64
#define KSc  4
#define REDc 128
#define Mc   (Bc * Tc)   // 16384 tokens

// ---------------- scratch (device globals; no allocation allowed) ----------------
// Referenced directly by symbol inside kernels -> kernel_launch stays pure launches.
__device__ float g_Q[Mc * HIDc];         // 64 MB : Q projection (pre-RoPE)
__device__ float g_V[Mc * HIDc];         // 64 MB : V projection
__device__ float g_H1[Mc * REDc];        //  8 MB : silu(x@kg_w1+b1)
__device__ float g_kern[Mc * NHc * KSc]; //  4 MB : per-token conv kernels
__device__ float g_u[Mc * NHc];          //  1 MB : gate u
__device__ float g_vg[Mc * NHc];         //  1 MB : gate v
__device__ float g_Vmix[Mc * HIDc];      // 64 MB
__device__ float g_S[Mc * HIDc];         // 64 MB : scan output

// ---------------- packed f32x2 helpers (Blackwell dual-FMA path) ----------------
__device__ __forceinline__ unsigned long long pack2(float lo, float hi) {
    unsigned long long r;
    asm("mov.b64 %0, {%1, %2};" : "=l"(r) : "f"(lo), "f"(hi));
    return r;
}
__device__ __forceinline__ void fma2(unsigned long long& d, unsigned long long a, unsigned long long b) {
    asm("fma.rn.f32x2 %0, %1, %2, %0;" : "+l"(d) : "l"(a), "l"(b));
}
__device__ __forceinline__ float2 unpack2(unsigned long long v) {
    float2 f;
    asm("mov.b64 {%0, %1}, %2;" : "=f"(f.x), "=f"(f.y) : "l"(v));
    return f;
}

// ---------------- tiled fp32 GEMM: C[M,N] = A[M,K] @ B[K,N] + bias, opt silu ----
// BM=128, BN=128, BK=8, 256 threads, 8x8 per thread (accumulated as 8x4 f32x2).
#define BM 128
#define BN 128
#define BKT 8
#define TM 8
#define TN 8

template <int ACT>   // 0 = none, 1 = silu
__device__ __forceinline__ void gemm_body(
    const float* __restrict__ A, const float* __restrict__ Bm,
    const float* __restrict__ bias, float* __restrict__ C,
    int N_, int K_)
{
    __shared__ float As[BKT][BM];
    __shared__ float Bs[BKT][BN];

    const int tid  = threadIdx.x;
    const int brow = blockIdx.y * BM;
    const int bcol = blockIdx.x * BN;

    const int arow = tid >> 1;          // 0..127
    const int acol = (tid & 1) * 4;     // 0 or 4
    const int brl  = tid >> 5;          // 0..7
    const int bcl  = (tid & 31) * 4;    // 0..124

    const int ty = tid >> 4;            // 0..15
    const int tx = tid & 15;            // 0..15

    unsigned long long acc2[TM][TN / 2];
    #pragma unroll
    for (int i = 0; i < TM; i++)
        #pragma unroll
        for (int j = 0; j < TN / 2; j++) acc2[i][j] = 0ULL;

    const float* Ap = A  + (size_t)(brow + arow) * K_ + acol;
    const float* Bp = Bm + (size_t)brl * N_ + bcol + bcl;

    float4 av = *(const float4*)Ap;
    float4 bv = *(const float4*)Bp;

    for (int k0 = 0; k0 < K_; k0 += BKT) {
        As[acol + 0][arow] = av.x;
        As[acol + 1][arow] = av.y;
        As[acol + 2][arow] = av.z;
        As[acol + 3][arow] = av.w;
        *(float4*)&Bs[brl][bcl] = bv;
        __syncthreads();

        if (k0 + BKT < K_) {   // prefetch next tile while computing
            av = *(const float4*)(Ap + k0 + BKT);
            bv = *(const float4*)(Bp + (size_t)(k0 + BKT) * N_);
        }

        #pragma unroll
        for (int k = 0; k < BKT; k++) {
            float4 a0 = *(const float4*)&As[k][ty * TM];
            float4 a1 = *(const float4*)&As[k][ty * TM + 4];
            float4 b0 = *(const float4*)&Bs[k][tx * TN];
            float4 b1 = *(const float4*)&Bs[k][tx * TN + 4];
            unsigned long long bp[4] = {
                pack2(b0.x, b0.y), pack2(b0.z, b0.w),
                pack2(b1.x, b1.y), pack2(b1.z, b1.w)
            };
            float aa[8] = {a0.x, a0.y, a0.z, a0.w, a1.x, a1.y, a1.z, a1.w};
            #pragma unroll
            for (int i = 0; i < TM; i++) {
                unsigned long long ap = pack2(aa[i], aa[i]);
                #pragma unroll
                for (int j = 0; j < TN / 2; j++) fma2(acc2[i][j], ap, bp[j]);
            }
        }
        __syncthreads();
    }

    #pragma unroll
    for (int i = 0; i < TM; i++) {
        const int row = brow + ty * TM + i;
        const int col = bcol + tx * TN;
        float ov[8];
        #pragma unroll
        for (int j = 0; j < TN / 2; j++) {
            float2 p = unpack2(acc2[i][j]);
            ov[2 * j]     = p.x + bias[col + 2 * j];
            ov[2 * j + 1] = p.y + bias[col + 2 * j + 1];
        }
        if (ACT == 1) {
            #pragma unroll
            for (int j = 0; j < 8; j++) ov[j] = ov[j] / (1.0f + expf(-ov[j]));
        }
        float* cp = C + (size_t)row * N_ + col;
        *(float4*)(cp)     = make_float4(ov[0], ov[1], ov[2], ov[3]);
        *(float4*)(cp + 4) = make_float4(ov[4], ov[5], ov[6], ov[7]);
    }
}

// Specializations binding scratch symbols directly (no host-side symbol lookup)
__global__ void __launch_bounds__(256) gemm_q(const float* __restrict__ x,
                                              const float* __restrict__ W,
                                              const float* __restrict__ b) {
    gemm_body<0>(x, W, b, g_Q, HIDc, HIDc);
}
__global__ void __launch_bounds__(256) gemm_v(const float* __restrict__ x,
                                              const float* __restrict__ W,
                                              const float* __restrict__ b) {
    gemm_body<0>(x, W, b, g_V, HIDc, HIDc);
}
__global__ void __launch_bounds__(256) gemm_h1(const float* __restrict__ x,
                                               const float* __restrict__ W,
                                               const float* __restrict__ b) {
    gemm_body<1>(x, W, b, g_H1, REDc, HIDc);
}
__global__ void __launch_bounds__(256) gemm_out(const float* __restrict__ W,
                                                const float* __restrict__ b,
                                                float* __restrict__ out) {
    gemm_body<0>(g_S, W, b, out, HIDc, HIDc);
}

// ---------------- kernels MLP second layer: [M,128] @ [128,64] + b ----------------
__global__ void __launch_bounds__(256) kern_gemm(
    const float* __restrict__ W2, const float* __restrict__ b2)
{
    __shared__ float Ws[REDc * 64];   // 32 KB
    __shared__ float Hs[32 * REDc];   // 16 KB
    const int tid  = threadIdx.x;
    const int row0 = blockIdx.x * 32;

    for (int i = tid; i < REDc * 64 / 4; i += 256)
        ((float4*)Ws)[i] = ((const float4*)W2)[i];
    for (int i = tid; i < 32 * REDc / 4; i += 256)
        ((float4*)Hs)[i] = ((const float4*)(g_H1 + (size_t)row0 * REDc))[i];
    __syncthreads();

    const int c  = tid & 63;   // 0..63
    const int rg = tid >> 6;   // 0..3
    #pragma unroll
    for (int rr = 0; rr < 8; rr++) {
        const int r = rg + rr * 4;
        float acc = b2[c];
        #pragma unroll 8
        for (int k = 0; k < REDc; k++)
            acc = fmaf(Hs[r * REDc + k], Ws[k * 64 + c], acc);
        g_kern[(size_t)(row0 + r) * 64 + c] = acc;
    }
}

// ---------------- RoPE + gate: one warp per (token, head) ----------------
__global__ void __launch_bounds__(256) gate_kernel(
    const float* __restrict__ gw, const float* __restrict__ gb)
{
    const int warp = blockIdx.x * 8 + (threadIdx.x >> 5);
    const int lane = threadIdx.x & 31;
    const int m = warp >> 4;           // token
    const int h = warp & 15;           // head
    const int t = m & (Tc - 1);        // position within sequence

    const float* q = g_Q + (size_t)m * HIDc + h * QKc;
    const float q1 = q[lane];
    const float q2 = q[lane + 32];

    // freq_j = 10000^(-j/16) = exp(-j * ln(10000)/16)
    const float fr = expf(-(float)lane * 0.57564627324851142f);
    float ang = (float)((double)t * (double)fr);
    float sn, cs;
    sincosf(ang, &sn, &cs);
    const float r0 = q1 * cs - q2 * sn;
    const float r1 = q1 * sn + q2 * cs;

    float cu = r0 * gw[2 * lane]     + r1 * gw[2 * (lane + 32)];
    float cv = r0 * gw[2 * lane + 1] + r1 * gw[2 * (lane + 32) + 1];
    #pragma unroll
    for (int o = 16; o; o >>= 1) {
        cu += __shfl_xor_sync(0xFFFFFFFFu, cu, o);
        cv += __shfl_xor_sync(0xFFFFFFFFu, cv, o);
    }
    if (lane == 0) {
        g_u [(size_t)m * NHc + h] = 1.0f / (1.0f + expf(-(cu + gb[0])));
        g_vg[(size_t)m * NHc + h] = 1.0f / (1.0f + expf(-(cv + gb[1])));
    }
}

// ---------------- causal depthwise mix over time (KS=4) ----------------
__global__ void __launch_bounds__(256) vmix_kernel()
{
    const int i = blockIdx.x * 256 + threadIdx.x;   // over M*1024
    const int m   = i >> 10;
    const int rem = i & 1023;
    const int h   = rem >> 6;
    const int t   = m & (Tc - 1);
    const float* kp = g_kern + (size_t)m * (NHc * KSc) + h * KSc;
    float acc = 0.0f;
    #pragma unroll
    for (int k = 0; k < KSc; k++) {
        const int dt = k - (KSc - 1);
        if (t + dt >= 0) acc = fmaf(kp[k], g_V[i + dt * HIDc], acc);
    }
    g_Vmix[i] = acc;
}

// ---------------- sequential scan: one warp per 32 (b,h,d) lanes ----------------
__global__ void __launch_bounds__(32) scan_kernel()
{
    const int g  = blockIdx.x * 32 + threadIdx.x;   // 0..4095
    const int d  = g & 63;
    const int bh = g >> 6;
    const int h  = bh & 15;
    const int b  = bh >> 4;

    const size_t base_uv = (size_t)b * Tc * NHc + h;
    const size_t base_x  = (size_t)b * Tc * HIDc + h * 64 + d;

    float s = 0.0f;
    #pragma unroll 4
    for (int t = 0; t < Tc; t++) {
        const float u = __ldg(g_u  + base_uv + (size_t)t * NHc);
        const float v = __ldg(g_vg + base_uv + (size_t)t * NHc);
        const float w = g_Vmix[base_x + (size_t)t * HIDc] * v;
        s = fmaf(u, s, w);
        g_S[base_x + (size_t)t * HIDc] = s;
    }
}

// ---------------- launcher: pure kernel launches (graph-capture safe) ----------------
extern "C" void kernel_launch(void* const* d_in, const int* in_sizes, int n_in,
                              void* d_out, int out_size)
{
    const float* x      = (const float*)d_in[0];
    const float* W_q    = (const float*)d_in[1];
    const float* b_q    = (const float*)d_in[2];
    // d_in[3] = W_k, d_in[4] = b_k : dead code in the reference -> skipped
    const float* W_v    = (const float*)d_in[5];
    const float* b_v    = (const float*)d_in[6];
    const float* kg_w1  = (const float*)d_in[7];
    const float* kg_b1  = (const float*)d_in[8];
    const float* kg_w2  = (const float*)d_in[9];
    const float* kg_b2  = (const float*)d_in[10];
    const float* gate_w = (const float*)d_in[11];
    const float* gate_b = (const float*)d_in[12];
    const float* W_out  = (const float*)d_in[13];
    const float* b_out  = (const float*)d_in[14];
    float* out = (float*)d_out;

    // 1) Q projection
    gemm_q <<<dim3(HIDc / BN, Mc / BM), 256>>>(x, W_q, b_q);
    // 2) V projection
    gemm_v <<<dim3(HIDc / BN, Mc / BM), 256>>>(x, W_v, b_v);
    // 3) kernel-gate MLP layer 1 (+ silu)
    gemm_h1<<<dim3(REDc / BN, Mc / BM), 256>>>(x, kg_w1, kg_b1);
    // 4) kernel-gate MLP layer 2
    kern_gemm<<<Mc / 32, 256>>>(kg_w2, kg_b2);
    // 5) RoPE + gate (u, v)
    gate_kernel<<<(Mc * NHc) / 8, 256>>>(gate_w, gate_b);
    // 6) causal depthwise V mix
    vmix_kernel<<<(Mc * HIDc) / 256, 256>>>();
    // 7) linear recurrence scan
    scan_kernel<<<(Bc * NHc * VDc) / 32, 32>>>();
    // 8) output projection -> d_out
    gemm_out<<<dim3(HIDc / BN, Mc / BM), 256>>>(W_out, b_out, out);
}

// round 9
// speedup vs baseline: 1.0858x; 1.0858x over previous
#include <cuda_runtime.h>
#include <cuda_bf16.h>
#include <cstdint>
#include <math.h>

// Problem constants
#define Bc   4
#define Tc   4096
#define HIDc 1024
#define NHc  16
#define QKc  64
#define VDc  64
#define KSc  4
#define REDc 128
#define Mc   (Bc * Tc)   // 16384 tokens
#define KH   1024        // logical K of every GEMM

// ---------------- scratch: EXACTLY the R2 (guard-clean) set ----------------
__device__ float g_Q[Mc * HIDc];
__device__ float g_V[Mc * HIDc];
__device__ float g_H1[Mc * REDc];
__device__ float g_kern[Mc * NHc * KSc];
__device__ float g_u[Mc * NHc];
__device__ float g_vg[Mc * NHc];
__device__ float g_Vmix[Mc * HIDc];
__device__ float g_S[Mc * HIDc];

// ---------------- mma macro (scalar operands only) ----------------
#define MMA16816(c0, c1, c2, c3, a0, a1, a2, a3, b0, b1)                     \
    asm volatile("mma.sync.aligned.m16n8k16.row.col.f32.bf16.bf16.f32 "      \
        "{%0,%1,%2,%3}, {%4,%5,%6,%7}, {%8,%9}, {%0,%1,%2,%3};"              \
        : "+f"(c0), "+f"(c1), "+f"(c2), "+f"(c3)                             \
        : "r"(a0), "r"(a1), "r"(a2), "r"(a3), "r"(b0), "r"(b1))

#define DECLC(mi, ni) \
    float c##mi##ni##0 = 0.f, c##mi##ni##1 = 0.f, c##mi##ni##2 = 0.f, c##mi##ni##3 = 0.f

#define TRIPLE(mi, ni)                                                          \
    MMA16816(c##mi##ni##0, c##mi##ni##1, c##mi##ni##2, c##mi##ni##3,            \
             ah##mi##0, ah##mi##1, ah##mi##2, ah##mi##3, bh##ni##0, bh##ni##1); \
    MMA16816(c##mi##ni##0, c##mi##ni##1, c##mi##ni##2, c##mi##ni##3,            \
             ah##mi##0, ah##mi##1, ah##mi##2, ah##mi##3, bl##ni##0, bl##ni##1); \
    MMA16816(c##mi##ni##0, c##mi##ni##1, c##mi##ni##2, c##mi##ni##3,            \
             al##mi##0, al##mi##1, al##mi##2, al##mi##3, bh##ni##0, bh##ni##1)

// A fragments from smem: row stride 24 bf16 (48B, conflict-free for 32-bit LDS)
#define LDA(mi) {                                                            \
    const int o_ = (wm + mi * 16 + (lane >> 2)) * 24 + (lane & 3) * 2;       \
    ah##mi##0 = *(const uint32_t*)(pAh + o_);                                \
    ah##mi##1 = *(const uint32_t*)(pAh + o_ + 192);                          \
    ah##mi##2 = *(const uint32_t*)(pAh + o_ + 8);                            \
    ah##mi##3 = *(const uint32_t*)(pAh + o_ + 200);                          \
    al##mi##0 = *(const uint32_t*)(pAl + o_);                                \
    al##mi##1 = *(const uint32_t*)(pAl + o_ + 192);                          \
    al##mi##2 = *(const uint32_t*)(pAl + o_ + 8);                            \
    al##mi##3 = *(const uint32_t*)(pAl + o_ + 200); }

#define LDB(ni) {                                                            \
    const int o_ = (wn + ni * 8 + (lane >> 2)) * 24 + (lane & 3) * 2;        \
    bh##ni##0 = *(const uint32_t*)(pBh + o_);                                \
    bh##ni##1 = *(const uint32_t*)(pBh + o_ + 8);                            \
    bl##ni##0 = *(const uint32_t*)(pBl + o_);                                \
    bl##ni##1 = *(const uint32_t*)(pBl + o_ + 8); }

#define EPI(mi, ni) {                                                        \
    const int col_ = bcol + wn + ni * 8 + (lane & 3) * 2;                    \
    const float bb0_ = bias[col_], bb1_ = bias[col_ + 1];                    \
    float v0_ = c##mi##ni##0 + bb0_, v1_ = c##mi##ni##1 + bb1_;              \
    float v2_ = c##mi##ni##2 + bb0_, v3_ = c##mi##ni##3 + bb1_;              \
    if (ACT == 1) {                                                          \
        v0_ = v0_ / (1.0f + expf(-v0_)); v1_ = v1_ / (1.0f + expf(-v1_));    \
        v2_ = v2_ / (1.0f + expf(-v2_)); v3_ = v3_ / (1.0f + expf(-v3_));    \
    }                                                                        \
    const int row_ = brow + wm + mi * 16 + (lane >> 2);                      \
    *(float2*)(C + (size_t)row_ * N_ + col_)       = make_float2(v0_, v1_);  \
    *(float2*)(C + (size_t)(row_ + 8) * N_ + col_) = make_float2(v2_, v3_); }

__device__ __forceinline__ uint32_t pk2(__nv_bfloat16 a, __nv_bfloat16 b) {
    return (uint32_t)__bfloat16_as_ushort(a) | ((uint32_t)__bfloat16_as_ushort(b) << 16);
}
#define SPLIT1(x, h, l) { h = __float2bfloat16(x); l = __float2bfloat16((x) - __bfloat162float(h)); }

// ---------------- HMMA GEMM with IN-KERNEL bf16 hi/lo split ----------------
// C[M x N_] fp32 = A[M x 1024] fp32 @ W[1024 x N_] fp32 + bias, optional silu.
// 3-term split: hi*hi + hi*lo + lo*hi. CTA tile 128x64, BK=16, 8 warps (4x2) of 32x32.
// Plain LDG->STS double buffer (R2-style memory ops; no cp.async, no ldmatrix).
template <int ACT>
__device__ __forceinline__ void mma_gemm_body(
    const float* __restrict__ A, const float* __restrict__ Bm,
    const float* __restrict__ bias, float* __restrict__ C, int N_)
{
    __shared__ __align__(16) __nv_bfloat16 sAh[2][128 * 24];  // 12KB
    __shared__ __align__(16) __nv_bfloat16 sAl[2][128 * 24];  // 12KB
    __shared__ __align__(16) __nv_bfloat16 sBh[2][64 * 24];   //  6KB
    __shared__ __align__(16) __nv_bfloat16 sBl[2][64 * 24];   //  6KB

    const int tid  = threadIdx.x;
    const int wid  = tid >> 5;
    const int lane = tid & 31;
    const int brow = blockIdx.y * 128;
    const int bcol = blockIdx.x * 64;
    const int wm   = (wid >> 1) * 32;
    const int wn   = (wid & 1) * 32;

    // A load mapping: 128 rows x 16 cols fp32; thread -> row=tid>>1, 8 cols
    const int arow = tid >> 1;
    const int ac8  = (tid & 1) * 8;
    const float* gA = A + (size_t)(brow + arow) * KH + ac8;
    // B(W) load mapping: 16 k-rows x 64 n-cols; thread -> k=tid>>4, 4 cols
    const int bk  = tid >> 4;
    const int bn4 = (tid & 15) * 4;
    const float* gB = Bm + (size_t)bk * N_ + bcol + bn4;

    DECLC(0,0); DECLC(0,1); DECLC(0,2); DECLC(0,3);
    DECLC(1,0); DECLC(1,1); DECLC(1,2); DECLC(1,3);

    // prefetch chunk 0
    float4 va0 = *(const float4*)(gA);
    float4 va1 = *(const float4*)(gA + 4);
    float4 vb  = *(const float4*)(gB);

    #pragma unroll 1
    for (int it = 0; it < KH / 16; it++) {
        const int st = it & 1;
        // convert + store current chunk
        {
            __nv_bfloat16 h0,h1,h2,h3,h4,h5,h6,h7, l0,l1,l2,l3,l4,l5,l6,l7;
            SPLIT1(va0.x, h0, l0); SPLIT1(va0.y, h1, l1);
            SPLIT1(va0.z, h2, l2); SPLIT1(va0.w, h3, l3);
            SPLIT1(va1.x, h4, l4); SPLIT1(va1.y, h5, l5);
            SPLIT1(va1.z, h6, l6); SPLIT1(va1.w, h7, l7);
            uint4 H; H.x = pk2(h0,h1); H.y = pk2(h2,h3); H.z = pk2(h4,h5); H.w = pk2(h6,h7);
            uint4 L; L.x = pk2(l0,l1); L.y = pk2(l2,l3); L.z = pk2(l4,l5); L.w = pk2(l6,l7);
            *(uint4*)&sAh[st][arow * 24 + ac8] = H;
            *(uint4*)&sAl[st][arow * 24 + ac8] = L;

            __nv_bfloat16 bh0,bh1,bh2,bh3, bl0,bl1,bl2,bl3;
            SPLIT1(vb.x, bh0, bl0); SPLIT1(vb.y, bh1, bl1);
            SPLIT1(vb.z, bh2, bl2); SPLIT1(vb.w, bh3, bl3);
            sBh[st][(bn4 + 0) * 24 + bk] = bh0;  sBl[st][(bn4 + 0) * 24 + bk] = bl0;
            sBh[st][(bn4 + 1) * 24 + bk] = bh1;  sBl[st][(bn4 + 1) * 24 + bk] = bl1;
            sBh[st][(bn4 + 2) * 24 + bk] = bh2;  sBl[st][(bn4 + 2) * 24 + bk] = bl2;
            sBh[st][(bn4 + 3) * 24 + bk] = bh3;  sBl[st][(bn4 + 3) * 24 + bk] = bl3;
        }
        __syncthreads();

        // prefetch next chunk
        if (it + 1 < KH / 16) {
            const int k0 = (it + 1) * 16;
            va0 = *(const float4*)(gA + k0);
            va1 = *(const float4*)(gA + k0 + 4);
            vb  = *(const float4*)(gB + (size_t)k0 * N_);
        }

        // compute from smem[st]
        {
            const __nv_bfloat16* pAh = &sAh[st][0];
            const __nv_bfloat16* pAl = &sAl[st][0];
            const __nv_bfloat16* pBh = &sBh[st][0];
            const __nv_bfloat16* pBl = &sBl[st][0];
            uint32_t ah00, ah01, ah02, ah03, ah10, ah11, ah12, ah13;
            uint32_t al00, al01, al02, al03, al10, al11, al12, al13;
            uint32_t bh00, bh01, bh10, bh11, bh20, bh21, bh30, bh31;
            uint32_t bl00, bl01, bl10, bl11, bl20, bl21, bl30, bl31;
            LDA(0) LDA(1)
            LDB(0) LDB(1) LDB(2) LDB(3)
            TRIPLE(0,0); TRIPLE(0,1); TRIPLE(0,2); TRIPLE(0,3);
            TRIPLE(1,0); TRIPLE(1,1); TRIPLE(1,2); TRIPLE(1,3);
        }
        __syncthreads();
    }

    EPI(0,0) EPI(0,1) EPI(0,2) EPI(0,3)
    EPI(1,0) EPI(1,1) EPI(1,2) EPI(1,3)
}

__global__ void __launch_bounds__(256) tc_q(const float* __restrict__ x,
                                            const float* __restrict__ W,
                                            const float* __restrict__ b) {
    mma_gemm_body<0>(x, W, b, g_Q, HIDc);
}
__global__ void __launch_bounds__(256) tc_v(const float* __restrict__ x,
                                            const float* __restrict__ W,
                                            const float* __restrict__ b) {
    mma_gemm_body<0>(x, W, b, g_V, HIDc);
}
__global__ void __launch_bounds__(256) tc_h1(const float* __restrict__ x,
                                             const float* __restrict__ W,
                                             const float* __restrict__ b) {
    mma_gemm_body<1>(x, W, b, g_H1, REDc);
}
__global__ void __launch_bounds__(256) tc_out(const float* __restrict__ W,
                                              const float* __restrict__ b,
                                              float* __restrict__ out) {
    mma_gemm_body<0>(g_S, W, b, out, HIDc);
}

// ---------------- kernels MLP second layer: [M,128] @ [128,64] + b ----------------
__global__ void __launch_bounds__(256) kern_gemm(
    const float* __restrict__ W2, const float* __restrict__ b2)
{
    __shared__ float Ws[REDc * 64];
    __shared__ float Hs[32 * REDc];
    const int tid  = threadIdx.x;
    const int row0 = blockIdx.x * 32;

    for (int i = tid; i < REDc * 64 / 4; i += 256)
        ((float4*)Ws)[i] = ((const float4*)W2)[i];
    for (int i = tid; i < 32 * REDc / 4; i += 256)
        ((float4*)Hs)[i] = ((const float4*)(g_H1 + (size_t)row0 * REDc))[i];
    __syncthreads();

    const int c  = tid & 63;
    const int rg = tid >> 6;
    #pragma unroll
    for (int rr = 0; rr < 8; rr++) {
        const int r = rg + rr * 4;
        float acc = b2[c];
        #pragma unroll 8
        for (int k = 0; k < REDc; k++)
            acc = fmaf(Hs[r * REDc + k], Ws[k * 64 + c], acc);
        g_kern[(size_t)(row0 + r) * 64 + c] = acc;
    }
}

// ---------------- RoPE + gate ----------------
__global__ void __launch_bounds__(256) gate_kernel(
    const float* __restrict__ gw, const float* __restrict__ gb)
{
    const int warp = blockIdx.x * 8 + (threadIdx.x >> 5);
    const int lane = threadIdx.x & 31;
    const int m = warp >> 4;
    const int h = warp & 15;
    const int t = m & (Tc - 1);

    const float* q = g_Q + (size_t)m * HIDc + h * QKc;
    const float q1 = q[lane];
    const float q2 = q[lane + 32];

    const float fr = expf(-(float)lane * 0.57564627324851142f);
    float ang = (float)((double)t * (double)fr);
    float sn, cs;
    sincosf(ang, &sn, &cs);
    const float r0 = q1 * cs - q2 * sn;
    const float r1 = q1 * sn + q2 * cs;

    float cu = r0 * gw[2 * lane]     + r1 * gw[2 * (lane + 32)];
    float cv = r0 * gw[2 * lane + 1] + r1 * gw[2 * (lane + 32) + 1];
    #pragma unroll
    for (int o = 16; o; o >>= 1) {
        cu += __shfl_xor_sync(0xFFFFFFFFu, cu, o);
        cv += __shfl_xor_sync(0xFFFFFFFFu, cv, o);
    }
    if (lane == 0) {
        g_u [(size_t)m * NHc + h] = 1.0f / (1.0f + expf(-(cu + gb[0])));
        g_vg[(size_t)m * NHc + h] = 1.0f / (1.0f + expf(-(cv + gb[1])));
    }
}

// ---------------- causal depthwise mix ----------------
__global__ void __launch_bounds__(256) vmix_kernel()
{
    const int i = blockIdx.x * 256 + threadIdx.x;
    const int m   = i >> 10;
    const int rem = i & 1023;
    const int h   = rem >> 6;
    const int t   = m & (Tc - 1);
    const float* kp = g_kern + (size_t)m * (NHc * KSc) + h * KSc;
    float acc = 0.0f;
    #pragma unroll
    for (int k = 0; k < KSc; k++) {
        const int dt = k - (KSc - 1);
        if (t + dt >= 0) acc = fmaf(kp[k], g_V[i + dt * HIDc], acc);
    }
    g_Vmix[i] = acc;
}

// ---------------- sequential scan (fp32 out, exactly as R2) ----------------
__global__ void __launch_bounds__(32) scan_kernel()
{
    const int g  = blockIdx.x * 32 + threadIdx.x;
    const int d  = g & 63;
    const int bh = g >> 6;
    const int h  = bh & 15;
    const int b  = bh >> 4;

    const size_t base_uv = (size_t)b * Tc * NHc + h;
    const size_t base_x  = (size_t)b * Tc * HIDc + h * 64 + d;

    float s = 0.0f;
    #pragma unroll 4
    for (int t = 0; t < Tc; t++) {
        const float u = __ldg(g_u  + base_uv + (size_t)t * NHc);
        const float v = __ldg(g_vg + base_uv + (size_t)t * NHc);
        const float w = g_Vmix[base_x + (size_t)t * HIDc] * v;
        s = fmaf(u, s, w);
        g_S[base_x + (size_t)t * HIDc] = s;
    }
}

// ---------------- launcher (pure kernel launches) ----------------
extern "C" void kernel_launch(void* const* d_in, const int* in_sizes, int n_in,
                              void* d_out, int out_size)
{
    const float* x      = (const float*)d_in[0];
    const float* W_q    = (const float*)d_in[1];
    const float* b_q    = (const float*)d_in[2];
    // d_in[3]=W_k, d_in[4]=b_k : dead code in reference
    const float* W_v    = (const float*)d_in[5];
    const float* b_v    = (const float*)d_in[6];
    const float* kg_w1  = (const float*)d_in[7];
    const float* kg_b1  = (const float*)d_in[8];
    const float* kg_w2  = (const float*)d_in[9];
    const float* kg_b2  = (const float*)d_in[10];
    const float* gate_w = (const float*)d_in[11];
    const float* gate_b = (const float*)d_in[12];
    const float* W_out  = (const float*)d_in[13];
    const float* b_out  = (const float*)d_in[14];
    float* out = (float*)d_out;

    // HMMA GEMMs directly from fp32 inputs (split computed in-kernel)
    tc_q <<<dim3(HIDc / 64, Mc / 128), 256>>>(x, W_q, b_q);
    tc_v <<<dim3(HIDc / 64, Mc / 128), 256>>>(x, W_v, b_v);
    tc_h1<<<dim3(REDc / 64, Mc / 128), 256>>>(x, kg_w1, kg_b1);

    kern_gemm<<<Mc / 32, 256>>>(kg_w2, kg_b2);
    gate_kernel<<<(Mc * NHc) / 8, 256>>>(gate_w, gate_b);
    vmix_kernel<<<(Mc * HIDc) / 256, 256>>>();
    scan_kernel<<<(Bc * NHc * VDc) / 32, 32>>>();

    tc_out<<<dim3(HIDc / 64, Mc / 128), 256>>>(W_out, b_out, out);
}

// round 10
// speedup vs baseline: 1.1723x; 1.0797x over previous
#include <cuda_runtime.h>
#include <cuda_bf16.h>
#include <cstdint>
#include <math.h>

// Problem constants
#define Bc   4
#define Tc   4096
#define HIDc 1024
#define NHc  16
#define QKc  64
#define VDc  64
#define KSc  4
#define REDc 128
#define Mc   (Bc * Tc)   // 16384 tokens
#define KH   1024        // logical K
#define KP   2048        // split width (hi 0..1023 | lo 1024..2047)

// ---------------- scratch: EXACT R9 footprint (guard-proven) ----------------
__device__ __align__(256) float g_Q[Mc * HIDc];
__device__ __align__(256) float g_V[Mc * HIDc];
__device__ __align__(256) float g_H1[Mc * REDc];
__device__ __align__(256) float g_kern[Mc * NHc * KSc];
__device__ __align__(256) float g_u[Mc * NHc];
__device__ __align__(256) float g_vg[Mc * NHc];
__device__ __align__(256) float g_Vmix[Mc * HIDc];
__device__ __align__(256) float g_S[Mc * HIDc];

// Reinterpreted bf16 regions inside existing buffers:
//  Xs  = (bf16*)g_S      [Mc][2048]  : x split; consumed by tc_q/v/h1, then
//                                      overwritten by scan's split output Ss.
//  Wq  = (bf16*)g_Vmix + 0           [1024][2048]
//  Wv  = (bf16*)g_Vmix + 2097152     [1024][2048]
//  W1  = (bf16*)g_Vmix + 4194304     [128][2048]   (all dead before vmix runs)
//  Wo  = (bf16*)g_H1                 [1024][2048]  (written after kern_gemm)
#define WQ_OFF 0
#define WV_OFF 2097152
#define W1_OFF 4194304

// ---------------- mma macros (hardware-verified in R9; unchanged) ----------------
#define MMA16816(c0, c1, c2, c3, a0, a1, a2, a3, b0, b1)                     \
    asm volatile("mma.sync.aligned.m16n8k16.row.col.f32.bf16.bf16.f32 "      \
        "{%0,%1,%2,%3}, {%4,%5,%6,%7}, {%8,%9}, {%0,%1,%2,%3};"              \
        : "+f"(c0), "+f"(c1), "+f"(c2), "+f"(c3)                             \
        : "r"(a0), "r"(a1), "r"(a2), "r"(a3), "r"(b0), "r"(b1))

#define DECLC(mi, ni) \
    float c##mi##ni##0 = 0.f, c##mi##ni##1 = 0.f, c##mi##ni##2 = 0.f, c##mi##ni##3 = 0.f

#define TRIPLE(mi, ni)                                                          \
    MMA16816(c##mi##ni##0, c##mi##ni##1, c##mi##ni##2, c##mi##ni##3,            \
             ah##mi##0, ah##mi##1, ah##mi##2, ah##mi##3, bh##ni##0, bh##ni##1); \
    MMA16816(c##mi##ni##0, c##mi##ni##1, c##mi##ni##2, c##mi##ni##3,            \
             ah##mi##0, ah##mi##1, ah##mi##2, ah##mi##3, bl##ni##0, bl##ni##1); \
    MMA16816(c##mi##ni##0, c##mi##ni##1, c##mi##ni##2, c##mi##ni##3,            \
             al##mi##0, al##mi##1, al##mi##2, al##mi##3, bh##ni##0, bh##ni##1)

#define LDA(mi) {                                                            \
    const int o_ = (wm + mi * 16 + (lane >> 2)) * 24 + (lane & 3) * 2;       \
    ah##mi##0 = *(const uint32_t*)(pAh + o_);                                \
    ah##mi##1 = *(const uint32_t*)(pAh + o_ + 192);                          \
    ah##mi##2 = *(const uint32_t*)(pAh + o_ + 8);                            \
    ah##mi##3 = *(const uint32_t*)(pAh + o_ + 200);                          \
    al##mi##0 = *(const uint32_t*)(pAl + o_);                                \
    al##mi##1 = *(const uint32_t*)(pAl + o_ + 192);                          \
    al##mi##2 = *(const uint32_t*)(pAl + o_ + 8);                            \
    al##mi##3 = *(const uint32_t*)(pAl + o_ + 200); }

#define LDB(ni) {                                                            \
    const int o_ = (wn + ni * 8 + (lane >> 2)) * 24 + (lane & 3) * 2;        \
    bh##ni##0 = *(const uint32_t*)(pBh + o_);                                \
    bh##ni##1 = *(const uint32_t*)(pBh + o_ + 8);                            \
    bl##ni##0 = *(const uint32_t*)(pBl + o_);                                \
    bl##ni##1 = *(const uint32_t*)(pBl + o_ + 8); }

#define EPI(mi, ni) {                                                        \
    const int col_ = bcol + wn + ni * 8 + (lane & 3) * 2;                    \
    const float bb0_ = bias[col_], bb1_ = bias[col_ + 1];                    \
    float v0_ = c##mi##ni##0 + bb0_, v1_ = c##mi##ni##1 + bb1_;              \
    float v2_ = c##mi##ni##2 + bb0_, v3_ = c##mi##ni##3 + bb1_;              \
    if (ACT == 1) {                                                          \
        v0_ = v0_ / (1.0f + expf(-v0_)); v1_ = v1_ / (1.0f + expf(-v1_));    \
        v2_ = v2_ / (1.0f + expf(-v2_)); v3_ = v3_ / (1.0f + expf(-v3_));    \
    }                                                                        \
    const int row_ = brow + wm + mi * 16 + (lane >> 2);                      \
    *(float2*)(C + (size_t)row_ * N_ + col_)       = make_float2(v0_, v1_);  \
    *(float2*)(C + (size_t)(row_ + 8) * N_ + col_) = make_float2(v2_, v3_); }

__device__ __forceinline__ uint32_t pk2(__nv_bfloat16 a, __nv_bfloat16 b) {
    return (uint32_t)__bfloat16_as_ushort(a) | ((uint32_t)__bfloat16_as_ushort(b) << 16);
}
#define SPLIT1(x, h, l) { h = __float2bfloat16(x); l = __float2bfloat16((x) - __bfloat162float(h)); }

// ---------------- HMMA GEMM on pre-split bf16 operands ----------------
// C[M x N_] fp32 = A2[M x 2048](hi|lo) @ B2[N_ x 2048](hi|lo)^T + bias.
// 3-term: hi*hi + hi*lo + lo*hi. CTA 128x64, BK=16, 8 warps (4x2) of 32x32.
// gmem->smem is pure LDG.128 -> STS.128, conflict-free; zero in-loop convert.
template <int ACT>
__device__ __forceinline__ void mma_gemm_body(
    const __nv_bfloat16* __restrict__ A2, const __nv_bfloat16* __restrict__ B2,
    const float* __restrict__ bias, float* __restrict__ C, int N_)
{
    __shared__ __align__(16) __nv_bfloat16 sAh[2][128 * 24];  // 12KB
    __shared__ __align__(16) __nv_bfloat16 sAl[2][128 * 24];  // 12KB
    __shared__ __align__(16) __nv_bfloat16 sBh[2][64 * 24];   //  6KB
    __shared__ __align__(16) __nv_bfloat16 sBl[2][64 * 24];   //  6KB

    const int tid  = threadIdx.x;
    const int wid  = tid >> 5;
    const int lane = tid & 31;
    const int brow = blockIdx.y * 128;
    const int bcol = blockIdx.x * 64;
    const int wm   = (wid >> 1) * 32;
    const int wn   = (wid & 1) * 32;

    // A: 2 threads per row; each loads 16B hi + 16B lo of the 16-wide chunk
    const int aRow = tid >> 1;
    const int aH   = (tid & 1) * 8;
    const __nv_bfloat16* gAh = A2 + (size_t)(brow + aRow) * KP + aH;
    const __nv_bfloat16* gAl = gAh + KH;
    // B: 4 threads per row; (bq&1) selects k-half, (bq>>1) selects hi/lo
    const int bRow = tid >> 2;
    const int bq   = tid & 3;
    const int bKH  = (bq & 1) * 8;
    const int bHL  = bq >> 1;
    const __nv_bfloat16* gB = B2 + (size_t)(bcol + bRow) * KP + bHL * KH + bKH;

    DECLC(0,0); DECLC(0,1); DECLC(0,2); DECLC(0,3);
    DECLC(1,0); DECLC(1,1); DECLC(1,2); DECLC(1,3);

    // prefetch chunk 0
    uint4 vah = *(const uint4*)gAh;
    uint4 val = *(const uint4*)gAl;
    uint4 vb  = *(const uint4*)gB;

    #pragma unroll 1
    for (int it = 0; it < KH / 16; it++) {
        const int st = it & 1;
        *(uint4*)&sAh[st][aRow * 24 + aH] = vah;
        *(uint4*)&sAl[st][aRow * 24 + aH] = val;
        if (bHL) *(uint4*)&sBl[st][bRow * 24 + bKH] = vb;
        else     *(uint4*)&sBh[st][bRow * 24 + bKH] = vb;
        __syncthreads();

        if (it + 1 < KH / 16) {
            const int k0 = (it + 1) * 16;
            vah = *(const uint4*)(gAh + k0);
            val = *(const uint4*)(gAl + k0);
            vb  = *(const uint4*)(gB + k0);
        }

        {
            const __nv_bfloat16* pAh = &sAh[st][0];
            const __nv_bfloat16* pAl = &sAl[st][0];
            const __nv_bfloat16* pBh = &sBh[st][0];
            const __nv_bfloat16* pBl = &sBl[st][0];
            uint32_t ah00, ah01, ah02, ah03, ah10, ah11, ah12, ah13;
            uint32_t al00, al01, al02, al03, al10, al11, al12, al13;
            uint32_t bh00, bh01, bh10, bh11, bh20, bh21, bh30, bh31;
            uint32_t bl00, bl01, bl10, bl11, bl20, bl21, bl30, bl31;
            LDA(0) LDA(1)
            LDB(0) LDB(1) LDB(2) LDB(3)
            TRIPLE(0,0); TRIPLE(0,1); TRIPLE(0,2); TRIPLE(0,3);
            TRIPLE(1,0); TRIPLE(1,1); TRIPLE(1,2); TRIPLE(1,3);
        }
        __syncthreads();
    }

    EPI(0,0) EPI(0,1) EPI(0,2) EPI(0,3)
    EPI(1,0) EPI(1,1) EPI(1,2) EPI(1,3)
}

__global__ void __launch_bounds__(256) tc_q(const float* __restrict__ b) {
    mma_gemm_body<0>((const __nv_bfloat16*)g_S, (const __nv_bfloat16*)g_Vmix + WQ_OFF,
                     b, g_Q, HIDc);
}
__global__ void __launch_bounds__(256) tc_v(const float* __restrict__ b) {
    mma_gemm_body<0>((const __nv_bfloat16*)g_S, (const __nv_bfloat16*)g_Vmix + WV_OFF,
                     b, g_V, HIDc);
}
__global__ void __launch_bounds__(256) tc_h1(const float* __restrict__ b) {
    mma_gemm_body<1>((const __nv_bfloat16*)g_S, (const __nv_bfloat16*)g_Vmix + W1_OFF,
                     b, g_H1, REDc);
}
__global__ void __launch_bounds__(256) tc_out(const float* __restrict__ b,
                                              float* __restrict__ out) {
    mma_gemm_body<0>((const __nv_bfloat16*)g_S, (const __nv_bfloat16*)g_H1,
                     b, out, HIDc);
}

// ---------------- split kernels ----------------
// x[M x 1024] fp32 -> Xs[M x 2048] bf16 (hi|lo) into g_S region
__global__ void __launch_bounds__(256) split_x(const float* __restrict__ X) {
    __nv_bfloat16* D = (__nv_bfloat16*)g_S;
    const size_t i = (size_t)blockIdx.x * 256 + threadIdx.x;
    const size_t gi = i * 4;
    const size_t m = gi >> 10, k = gi & 1023;
    float4 v = *(const float4*)(X + gi);
    __nv_bfloat16 h0, h1, h2, h3, l0, l1, l2, l3;
    SPLIT1(v.x, h0, l0); SPLIT1(v.y, h1, l1);
    SPLIT1(v.z, h2, l2); SPLIT1(v.w, h3, l3);
    *(uint2*)(D + m * KP + k)      = make_uint2(pk2(h0, h1), pk2(h2, h3));
    *(uint2*)(D + m * KP + KH + k) = make_uint2(pk2(l0, l1), pk2(l2, l3));
}

// W[K x N] fp32 -> Wt[N x 2K] bf16 (transpose + hi/lo split), Wt given as offset region
__global__ void __launch_bounds__(1024) wsplit(const float* __restrict__ W,
                                               __nv_bfloat16* __restrict__ Wt,
                                               int K_, int N_)
{
    __shared__ float t[32][33];
    const int k = blockIdx.y * 32 + threadIdx.y;
    const int n = blockIdx.x * 32 + threadIdx.x;
    t[threadIdx.y][threadIdx.x] = W[(size_t)k * N_ + n];
    __syncthreads();
    const int n2 = blockIdx.x * 32 + threadIdx.y;
    const int k2 = blockIdx.y * 32 + threadIdx.x;
    const float v = t[threadIdx.x][threadIdx.y];
    __nv_bfloat16 h, l;
    SPLIT1(v, h, l);
    Wt[(size_t)n2 * (2 * K_) + k2]      = h;
    Wt[(size_t)n2 * (2 * K_) + K_ + k2] = l;
}
// wrappers binding the reused regions (no pointer args from host needed beyond W)
__global__ void __launch_bounds__(1024) wsplit_q(const float* __restrict__ W);
__global__ void __launch_bounds__(1024) wsplit_v(const float* __restrict__ W);

// ---------------- kernels MLP second layer: [M,128] @ [128,64] + b ----------------
__global__ void __launch_bounds__(256) kern_gemm(
    const float* __restrict__ W2, const float* __restrict__ b2)
{
    __shared__ float Ws[REDc * 64];
    __shared__ float Hs[32 * REDc];
    const int tid  = threadIdx.x;
    const int row0 = blockIdx.x * 32;

    for (int i = tid; i < REDc * 64 / 4; i += 256)
        ((float4*)Ws)[i] = ((const float4*)W2)[i];
    for (int i = tid; i < 32 * REDc / 4; i += 256)
        ((float4*)Hs)[i] = ((const float4*)(g_H1 + (size_t)row0 * REDc))[i];
    __syncthreads();

    const int c  = tid & 63;
    const int rg = tid >> 6;
    #pragma unroll
    for (int rr = 0; rr < 8; rr++) {
        const int r = rg + rr * 4;
        float acc = b2[c];
        #pragma unroll 8
        for (int k = 0; k < REDc; k++)
            acc = fmaf(Hs[r * REDc + k], Ws[k * 64 + c], acc);
        g_kern[(size_t)(row0 + r) * 64 + c] = acc;
    }
}

// ---------------- RoPE + gate ----------------
__global__ void __launch_bounds__(256) gate_kernel(
    const float* __restrict__ gw, const float* __restrict__ gb)
{
    const int warp = blockIdx.x * 8 + (threadIdx.x >> 5);
    const int lane = threadIdx.x & 31;
    const int m = warp >> 4;
    const int h = warp & 15;
    const int t = m & (Tc - 1);

    const float* q = g_Q + (size_t)m * HIDc + h * QKc;
    const float q1 = q[lane];
    const float q2 = q[lane + 32];

    const float fr = expf(-(float)lane * 0.57564627324851142f);
    float ang = (float)((double)t * (double)fr);
    float sn, cs;
    sincosf(ang, &sn, &cs);
    const float r0 = q1 * cs - q2 * sn;
    const float r1 = q1 * sn + q2 * cs;

    float cu = r0 * gw[2 * lane]     + r1 * gw[2 * (lane + 32)];
    float cv = r0 * gw[2 * lane + 1] + r1 * gw[2 * (lane + 32) + 1];
    #pragma unroll
    for (int o = 16; o; o >>= 1) {
        cu += __shfl_xor_sync(0xFFFFFFFFu, cu, o);
        cv += __shfl_xor_sync(0xFFFFFFFFu, cv, o);
    }
    if (lane == 0) {
        g_u [(size_t)m * NHc + h] = 1.0f / (1.0f + expf(-(cu + gb[0])));
        g_vg[(size_t)m * NHc + h] = 1.0f / (1.0f + expf(-(cv + gb[1])));
    }
}

// ---------------- causal depthwise mix ----------------
__global__ void __launch_bounds__(256) vmix_kernel()
{
    const int i = blockIdx.x * 256 + threadIdx.x;
    const int m   = i >> 10;
    const int rem = i & 1023;
    const int h   = rem >> 6;
    const int t   = m & (Tc - 1);
    const float* kp = g_kern + (size_t)m * (NHc * KSc) + h * KSc;
    float acc = 0.0f;
    #pragma unroll
    for (int k = 0; k < KSc; k++) {
        const int dt = k - (KSc - 1);
        if (t + dt >= 0) acc = fmaf(kp[k], g_V[i + dt * HIDc], acc);
    }
    g_Vmix[i] = acc;
}

// ---------------- sequential scan: emits bf16 hi|lo into g_S region ----------------
__global__ void __launch_bounds__(32) scan_kernel()
{
    __nv_bfloat16* Ss = (__nv_bfloat16*)g_S;
    const int g  = blockIdx.x * 32 + threadIdx.x;
    const int d  = g & 63;
    const int bh = g >> 6;
    const int h  = bh & 15;
    const int b  = bh >> 4;

    const size_t base_uv = (size_t)b * Tc * NHc + h;
    const size_t base_x  = (size_t)b * Tc * HIDc + h * 64 + d;
    const size_t base_s  = (size_t)b * Tc * KP + h * 64 + d;

    float s = 0.0f;
    #pragma unroll 4
    for (int t = 0; t < Tc; t++) {
        const float u = __ldg(g_u  + base_uv + (size_t)t * NHc);
        const float v = __ldg(g_vg + base_uv + (size_t)t * NHc);
        const float w = g_Vmix[base_x + (size_t)t * HIDc] * v;
        s = fmaf(u, s, w);
        __nv_bfloat16 hi, lo;
        SPLIT1(s, hi, lo);
        Ss[base_s + (size_t)t * KP]      = hi;
        Ss[base_s + (size_t)t * KP + KH] = lo;
    }
}

// ---- wsplit region-bound wrappers (defined after globals) ----
__global__ void __launch_bounds__(1024) wsplit_q(const float* __restrict__ W) {
    __shared__ float t[32][33];
    __nv_bfloat16* Wt = (__nv_bfloat16*)g_Vmix + WQ_OFF;
    const int k = blockIdx.y * 32 + threadIdx.y;
    const int n = blockIdx.x * 32 + threadIdx.x;
    t[threadIdx.y][threadIdx.x] = W[(size_t)k * HIDc + n];
    __syncthreads();
    const int n2 = blockIdx.x * 32 + threadIdx.y;
    const int k2 = blockIdx.y * 32 + threadIdx.x;
    const float v = t[threadIdx.x][threadIdx.y];
    __nv_bfloat16 h, l; SPLIT1(v, h, l);
    Wt[(size_t)n2 * KP + k2]      = h;
    Wt[(size_t)n2 * KP + KH + k2] = l;
}
__global__ void __launch_bounds__(1024) wsplit_v(const float* __restrict__ W) {
    __shared__ float t[32][33];
    __nv_bfloat16* Wt = (__nv_bfloat16*)g_Vmix + WV_OFF;
    const int k = blockIdx.y * 32 + threadIdx.y;
    const int n = blockIdx.x * 32 + threadIdx.x;
    t[threadIdx.y][threadIdx.x] = W[(size_t)k * HIDc + n];
    __syncthreads();
    const int n2 = blockIdx.x * 32 + threadIdx.y;
    const int k2 = blockIdx.y * 32 + threadIdx.x;
    const float v = t[threadIdx.x][threadIdx.y];
    __nv_bfloat16 h, l; SPLIT1(v, h, l);
    Wt[(size_t)n2 * KP + k2]      = h;
    Wt[(size_t)n2 * KP + KH + k2] = l;
}
__global__ void __launch_bounds__(1024) wsplit_1(const float* __restrict__ W) {
    __shared__ float t[32][33];
    __nv_bfloat16* Wt = (__nv_bfloat16*)g_Vmix + W1_OFF;
    const int k = blockIdx.y * 32 + threadIdx.y;
    const int n = blockIdx.x * 32 + threadIdx.x;
    t[threadIdx.y][threadIdx.x] = W[(size_t)k * REDc + n];
    __syncthreads();
    const int n2 = blockIdx.x * 32 + threadIdx.y;
    const int k2 = blockIdx.y * 32 + threadIdx.x;
    const float v = t[threadIdx.x][threadIdx.y];
    __nv_bfloat16 h, l; SPLIT1(v, h, l);
    Wt[(size_t)n2 * KP + k2]      = h;
    Wt[(size_t)n2 * KP + KH + k2] = l;
}
__global__ void __launch_bounds__(1024) wsplit_o(const float* __restrict__ W) {
    __shared__ float t[32][33];
    __nv_bfloat16* Wt = (__nv_bfloat16*)g_H1;
    const int k = blockIdx.y * 32 + threadIdx.y;
    const int n = blockIdx.x * 32 + threadIdx.x;
    t[threadIdx.y][threadIdx.x] = W[(size_t)k * HIDc + n];
    __syncthreads();
    const int n2 = blockIdx.x * 32 + threadIdx.y;
    const int k2 = blockIdx.y * 32 + threadIdx.x;
    const float v = t[threadIdx.x][threadIdx.y];
    __nv_bfloat16 h, l; SPLIT1(v, h, l);
    Wt[(size_t)n2 * KP + k2]      = h;
    Wt[(size_t)n2 * KP + KH + k2] = l;
}

// ---------------- launcher (pure kernel launches) ----------------
extern "C" void kernel_launch(void* const* d_in, const int* in_sizes, int n_in,
                              void* d_out, int out_size)
{
    const float* x      = (const float*)d_in[0];
    const float* W_q    = (const float*)d_in[1];
    const float* b_q    = (const float*)d_in[2];
    // d_in[3]=W_k, d_in[4]=b_k : dead code in reference
    const float* W_v    = (const float*)d_in[5];
    const float* b_v    = (const float*)d_in[6];
    const float* kg_w1  = (const float*)d_in[7];
    const float* kg_b1  = (const float*)d_in[8];
    const float* kg_w2  = (const float*)d_in[9];
    const float* kg_b2  = (const float*)d_in[10];
    const float* gate_w = (const float*)d_in[11];
    const float* gate_b = (const float*)d_in[12];
    const float* W_out  = (const float*)d_in[13];
    const float* b_out  = (const float*)d_in[14];
    float* out = (float*)d_out;

    // 1) one-shot operand splits into reused regions
    split_x<<<(Mc * HIDc / 4) / 256, 256>>>(x);                       // -> g_S region
    wsplit_q<<<dim3(HIDc / 32, HIDc / 32), dim3(32, 32)>>>(W_q);      // -> g_Vmix
    wsplit_v<<<dim3(HIDc / 32, HIDc / 32), dim3(32, 32)>>>(W_v);      // -> g_Vmix
    wsplit_1<<<dim3(REDc / 32, HIDc / 32), dim3(32, 32)>>>(kg_w1);    // -> g_Vmix

    // 2) HMMA GEMMs on pre-split operands
    tc_q <<<dim3(HIDc / 64, Mc / 128), 256>>>(b_q);
    tc_v <<<dim3(HIDc / 64, Mc / 128), 256>>>(b_v);
    tc_h1<<<dim3(REDc / 64, Mc / 128), 256>>>(kg_b1);

    // 3) small ops
    kern_gemm<<<Mc / 32, 256>>>(kg_w2, kg_b2);      // consumes g_H1
    wsplit_o<<<dim3(HIDc / 32, HIDc / 32), dim3(32, 32)>>>(W_out);    // -> g_H1 region
    gate_kernel<<<(Mc * NHc) / 8, 256>>>(gate_w, gate_b);
    vmix_kernel<<<(Mc * HIDc) / 256, 256>>>();      // writes g_Vmix (weight splits dead)
    scan_kernel<<<(Bc * NHc * VDc) / 32, 32>>>();   // writes Ss into g_S region (Xs dead)

    // 4) out projection from split scan output
    tc_out<<<dim3(HIDc / 64, Mc / 128), 256>>>(b_out, out);
}